// round 12
// baseline (speedup 1.0000x reference)
#include <cuda_runtime.h>
#include <cstdint>

#define N_NODES 500000
#define N_EDGES 16000000
#define BIT_WORDS 15625            // 500000 / 32 exactly
#define BIT_BYTES (BIT_WORDS * 4)  // 62500

// Per-node gain: relu(v[n]) * type_params[type[n]].  2 MB, stays L2-hot.
// ~50% of entries are exactly 0.0f (relu of N(0,1) voltage).
__device__ float    g_gain[N_NODES];
// 1 bit per node: g_gain[n] != 0.  62.5 KB -> fits in SMEM per block.
__device__ unsigned g_bits[BIT_WORDS];

// ---------------------------------------------------------------------------
// Kernel A: node prep. g_gain, zero-bitmap, out[n] = -v + stim + Vrest
// ---------------------------------------------------------------------------
__global__ void node_prep(const float* __restrict__ voltage,
                          const float* __restrict__ stimulus,
                          const int*   __restrict__ ntype,      // int32 (JAX x64 off)
                          const float* __restrict__ v_rest,
                          const float* __restrict__ type_params,
                          float* __restrict__ out,
                          int n)
{
    int i = blockIdx.x * blockDim.x + threadIdx.x;
    float g = 0.0f;
    if (i < n) {
        float v = voltage[i];
        float r = fmaxf(v, 0.0f);
        int t = ntype[i];                 // values in [0,64)
        g = r * __ldg(&type_params[t]);
        g_gain[i] = g;
        out[i] = -v + stimulus[i] + v_rest[i];
    }
    unsigned b = __ballot_sync(0xffffffffu, g != 0.0f);
    if ((threadIdx.x & 31) == 0 && i < n) {
        g_bits[i >> 5] = b;               // warp base i -> word i/32 (< BIT_WORDS)
    }
}

// ---------------------------------------------------------------------------
// Hard-predicated gather + scatter (the R9 form that measured fastest):
// one ISETP guards both the gather load and the no-return atomic; when
// bit==0 NEITHER issues a memory transaction. Single fused volatile block.
// ---------------------------------------------------------------------------
__device__ __forceinline__ void edge_op(int bit, const float* gaddr,
                                        float w, float* oaddr)
{
    asm volatile(
        "{\n\t"
        ".reg .pred p;\n\t"
        ".reg .f32  g, m;\n\t"
        "setp.ne.s32 p, %0, 0;\n\t"
        "mov.f32 g, 0f00000000;\n\t"
        "@p ld.global.nc.f32 g, [%1];\n\t"
        "mul.f32 m, g, %2;\n\t"
        "@p red.global.add.f32 [%3], m;\n\t"
        "}"
        :: "r"(bit), "l"(gaddr), "f"(w), "l"(oaddr) : "memory");
}

// ---------------------------------------------------------------------------
// Kernel B: persistent edge scatter with SMEM zero-bitmap, 8 edges/thread.
// 6 front-batched stream LDG.128s amortize loop/issue overhead; per edge
// one LDS bit-test + fused predicated gather/RED.
// ---------------------------------------------------------------------------
__global__ void __launch_bounds__(256) edge_scatter(
    const int4*   __restrict__ src4,   // edge_index row 0, int32 x4
    const int4*   __restrict__ dst4,   // edge_index row 1, int32 x4
    const float4* __restrict__ w4,
    float*        __restrict__ out,
    int n_groups8)                     // N_EDGES / 8
{
    extern __shared__ unsigned sbits[];

    // Cooperative bitmap load.
    for (int j = threadIdx.x; j < BIT_WORDS; j += blockDim.x)
        sbits[j] = g_bits[j];
    __syncthreads();

    int stride = gridDim.x * blockDim.x;
    for (int i = blockIdx.x * blockDim.x + threadIdx.x; i < n_groups8; i += stride) {
        // 6 independent 128-bit streaming loads, evict-first.
        int4   sa = __ldcs(&src4[2 * i]);
        int4   sb = __ldcs(&src4[2 * i + 1]);
        int4   da = __ldcs(&dst4[2 * i]);
        int4   db = __ldcs(&dst4[2 * i + 1]);
        float4 wa = __ldcs(&w4[2 * i]);
        float4 wb = __ldcs(&w4[2 * i + 1]);

        int b0 = (sbits[sa.x >> 5] >> (sa.x & 31)) & 1;
        int b1 = (sbits[sa.y >> 5] >> (sa.y & 31)) & 1;
        int b2 = (sbits[sa.z >> 5] >> (sa.z & 31)) & 1;
        int b3 = (sbits[sa.w >> 5] >> (sa.w & 31)) & 1;
        int b4 = (sbits[sb.x >> 5] >> (sb.x & 31)) & 1;
        int b5 = (sbits[sb.y >> 5] >> (sb.y & 31)) & 1;
        int b6 = (sbits[sb.z >> 5] >> (sb.z & 31)) & 1;
        int b7 = (sbits[sb.w >> 5] >> (sb.w & 31)) & 1;

        edge_op(b0, &g_gain[sa.x], wa.x, &out[da.x]);
        edge_op(b1, &g_gain[sa.y], wa.y, &out[da.y]);
        edge_op(b2, &g_gain[sa.z], wa.z, &out[da.z]);
        edge_op(b3, &g_gain[sa.w], wa.w, &out[da.w]);
        edge_op(b4, &g_gain[sb.x], wb.x, &out[db.x]);
        edge_op(b5, &g_gain[sb.y], wb.y, &out[db.y]);
        edge_op(b6, &g_gain[sb.z], wb.z, &out[db.z]);
        edge_op(b7, &g_gain[sb.w], wb.w, &out[db.w]);
    }
}

// ---------------------------------------------------------------------------
// Kernel C: out[n] = out[n] / tau[n]
// ---------------------------------------------------------------------------
__global__ void finalize(const float* __restrict__ tau,
                         float* __restrict__ out,
                         int n)
{
    int i = blockIdx.x * blockDim.x + threadIdx.x;
    if (i < n) {
        out[i] = out[i] / tau[i];
    }
}

// ---------------------------------------------------------------------------
// Launch
//   d_in: 0 voltage, 1 stimulus, 2 neuron_type(i32), 3 edge_index(i32 2xE),
//         4 w, 5 V_i_rest, 6 tau_i, 7 type_params
// ---------------------------------------------------------------------------
extern "C" void kernel_launch(void* const* d_in, const int* in_sizes, int n_in,
                              void* d_out, int out_size)
{
    const float* voltage = (const float*)d_in[0];
    const float* stim    = (const float*)d_in[1];
    const int*   ntype   = (const int*)d_in[2];
    const int*   eidx    = (const int*)d_in[3];
    const float* w       = (const float*)d_in[4];
    const float* vrest   = (const float*)d_in[5];
    const float* tau     = (const float*)d_in[6];
    const float* tparams = (const float*)d_in[7];
    float*       out     = (float*)d_out;

    const int n_nodes = N_NODES;
    const int n_edges = N_EDGES;

    // Allow >48KB dynamic smem for the bitmap kernel (idempotent, host-side).
    cudaFuncSetAttribute(edge_scatter,
                         cudaFuncAttributeMaxDynamicSharedMemorySize,
                         BIT_BYTES);

    // Kernel A
    {
        int threads = 256;
        int blocks = (n_nodes + threads - 1) / threads;
        node_prep<<<blocks, threads>>>(voltage, stim, ntype, vrest, tparams,
                                       out, n_nodes);
    }

    // Kernel B: persistent, 3 blocks/SM (62.5KB smem each), 256 thr/block
    {
        const int4*   src4 = (const int4*)(eidx);
        const int4*   dst4 = (const int4*)(eidx + n_edges);
        const float4* w4   = (const float4*)w;
        int n_groups8 = n_edges / 8;          // 2,000,000 (exact)
        int threads = 256;
        int blocks = 148 * 3;                 // persistent wave
        edge_scatter<<<blocks, threads, BIT_BYTES>>>(src4, dst4, w4, out,
                                                     n_groups8);
    }

    // Kernel C
    {
        int threads = 256;
        int blocks = (n_nodes + threads - 1) / threads;
        finalize<<<blocks, threads>>>(tau, out, n_nodes);
    }
}